// round 3
// baseline (speedup 1.0000x reference)
#include <cuda_runtime.h>
#include <cstdint>

#define NAG   4096
#define TOPK  12
#define NITEMS (NAG * TOPK)      // 49152
#define T1    256                // threads, topk kernel
#define EPT   16                 // elements per thread = 4096/256

// fused MLP tiling
#define TILE_I 128               // items per block
#define H1STR  132               // padded row stride (floats)
#define H2STR  132
#define SMEM_FLOATS (64 * H1STR + 128 * H2STR)
#define SMEM_BYTES  (SMEM_FLOATS * 4)   // 101,376 B dynamic

__device__ int   g_topk_idx[NITEMS];
__device__ float g_W2t[64 * 128];        // [k][m]
__device__ float g_W3t[128 * 64];        // [k][o]

// ---------------------------------------------------------------------------
// Kernel 1: per-row top-12. Load + per-thread bitonic sort (unchanged),
// then barrier-free warp-level merge: each warp emits its sorted top-12 via
// 12 shuffle-butterfly argmin passes; one __syncthreads; warp 0 merges the
// 96 candidates (3 per lane) with 12 more butterfly passes.
// ---------------------------------------------------------------------------
__global__ void __launch_bounds__(T1) topk_kernel(const float* __restrict__ x) {
    const int i    = blockIdx.x;
    const int tid  = threadIdx.x;
    const int w    = tid >> 5;
    const int lane = tid & 31;
    const float* row = x + (size_t)i * (NAG * 4);

    unsigned long long keys[EPT];
#pragma unroll
    for (int t = 0; t < EPT; ++t) {
        const int j = tid + t * T1;
        const float2 v = *reinterpret_cast<const float2*>(row + (size_t)j * 4);
        const float s = __fadd_rn(__fadd_rn(__fmul_rn(v.x, v.x), 1e-6f),
                                  __fadd_rn(__fmul_rn(v.y, v.y), 1e-6f));
        const float dn = __fsqrt_rn(s);
        keys[t] = ((unsigned long long)__float_as_uint(dn) << 32) | (unsigned)j;
    }

    // fully-unrolled bitonic sort of 16 keys, ascending, in registers
#pragma unroll
    for (int kk = 2; kk <= EPT; kk <<= 1) {
#pragma unroll
        for (int jj = kk >> 1; jj > 0; jj >>= 1) {
#pragma unroll
            for (int ii = 0; ii < EPT; ++ii) {
                const int ll = ii ^ jj;
                if (ll > ii) {
                    const bool up = ((ii & kk) == 0);
                    const unsigned long long a = keys[ii];
                    const unsigned long long b = keys[ll];
                    const bool sw = up ? (a > b) : (a < b);
                    if (sw) { keys[ii] = b; keys[ll] = a; }
                }
            }
        }
    }

    // stage 1: per-warp sorted top-12 (shuffle-only, no barriers)
    __shared__ unsigned long long warp12[(T1 / 32) * TOPK];   // [8][12]
    {
        int head = 0;
#pragma unroll
        for (int pass = 0; pass < TOPK; ++pass) {
            const unsigned long long mykey = keys[head];   // head <= 12 < 16
            unsigned long long v = mykey;
#pragma unroll
            for (int off = 16; off > 0; off >>= 1) {
                const unsigned long long o = __shfl_xor_sync(0xffffffffu, v, off);
                v = (o < v) ? o : v;
            }
            if (mykey == v) head++;        // keys unique -> exactly one lane
            if (lane == 0) warp12[w * TOPK + pass] = v;
        }
    }
    __syncthreads();

    // stage 2: warp 0 merges 96 candidates, 3 per lane
    if (w == 0) {
        unsigned long long c0 = warp12[lane];
        unsigned long long c1 = warp12[lane + 32];
        unsigned long long c2 = warp12[lane + 64];
#pragma unroll
        for (int pass = 0; pass < TOPK; ++pass) {
            unsigned long long m = (c0 < c1) ? c0 : c1;
            m = (c2 < m) ? c2 : m;
            unsigned long long v = m;
#pragma unroll
            for (int off = 16; off > 0; off >>= 1) {
                const unsigned long long o = __shfl_xor_sync(0xffffffffu, v, off);
                v = (o < v) ? o : v;
            }
            if (c0 == v)      c0 = 0xFFFFFFFFFFFFFFFFULL;
            else if (c1 == v) c1 = 0xFFFFFFFFFFFFFFFFULL;
            else if (c2 == v) c2 = 0xFFFFFFFFFFFFFFFFULL;
            if (lane == 0)
                g_topk_idx[i * TOPK + pass] = (int)(unsigned)(v & 0xFFFFFFFFULL);
        }
    }
}

// ---------------------------------------------------------------------------
// Kernel T: transpose W2 [128m][64k] -> W2t [64k][128m],
//           W3 [64o][128m] -> W3t [128m][64o]
// ---------------------------------------------------------------------------
__global__ void __launch_bounds__(256) transpose_kernel(
    const float* __restrict__ W2, const float* __restrict__ W3)
{
    const int tid = threadIdx.x;
    for (int s = tid; s < 128 * 64; s += 256) {
        const int m = s >> 6, k = s & 63;
        g_W2t[k * 128 + m] = W2[s];
    }
    for (int s = tid; s < 64 * 128; s += 256) {
        const int o = s >> 7, m = s & 127;
        g_W3t[m * 64 + o] = W3[s];
    }
}

// ---------------------------------------------------------------------------
// Fused MLP kernel: per block = 128 items, all of
//   feat+layer1 -> H1s(smem) -> layer2 GEMM -> H2s(smem) -> layer3 GEMM
//   -> layer4 reduction -> out.
// Dynamic smem: H1s [64][132] + H2s [128][132] = ~101 KB, 2 blocks/SM.
// Weight matrices W2t/W3t read via LDG (32 KB each, L1-resident).
// ---------------------------------------------------------------------------
__global__ void __launch_bounds__(256, 2) fused_mlp_kernel(
    const float* __restrict__ x,  const float* __restrict__ rp,
    const float* __restrict__ W1, const float* __restrict__ b1,
    const float* __restrict__ b2, const float* __restrict__ b3,
    const float* __restrict__ W4, const float* __restrict__ b4,
    float* __restrict__ out)
{
    extern __shared__ float smem[];
    float* H1s = smem;                   // [64][H1STR]
    float* H2s = smem + 64 * H1STR;      // [128][H2STR]
    float* red = smem;                   // reuse H1s area in stage C

    __shared__ float W1s[64 * 6];
    __shared__ float b1s[64];
    __shared__ float masks[TILE_I];

    const int tid = threadIdx.x;
    for (int s = tid; s < 384; s += 256) W1s[s] = W1[s];
    if (tid < 64) b1s[tid] = b1[tid];
    __syncthreads();

    // ---------------- stage A: features + layer1 (6 -> 64) ----------------
    {
        const int iloc = tid & 127;
        const int half = tid >> 7;           // 2 threads per item
        const int item = blockIdx.x * TILE_I + iloc;
        const int i = item / TOPK;
        const int j = g_topk_idx[item];

        const float4 v = *reinterpret_cast<const float4*>(
            x + ((size_t)i * NAG + (size_t)j) * 4);
        const float s2 = __fadd_rn(__fadd_rn(__fmul_rn(v.x, v.x), 1e-4f),
                                   __fadd_rn(__fmul_rn(v.y, v.y), 1e-4f));
        const float dn = __fsqrt_rn(s2);
        const float r  = rp[0];
        const float mk = (dn <= 1.0f) ? 1.0f : 0.0f;
        const float f0 = v.x, f1 = v.y, f2 = v.z, f3 = v.w;
        const float f4 = (i == j) ? 1.0f : 0.0f;
        const float f5 = dn - r;

        const int o0 = half * 32;
#pragma unroll
        for (int oo = 0; oo < 32; ++oo) {
            const int o = o0 + oo;
            const float* wp = W1s + o * 6;
            float a = b1s[o];
            a = fmaf(wp[0], f0, a); a = fmaf(wp[1], f1, a); a = fmaf(wp[2], f2, a);
            a = fmaf(wp[3], f3, a); a = fmaf(wp[4], f4, a); a = fmaf(wp[5], f5, a);
            H1s[o * H1STR + iloc] = fmaxf(a, 0.0f);
        }

        if (half == 0) {
            masks[iloc] = mk;
            out[NITEMS + item] = mk;
            out[2 * NITEMS + 2 * item + 0] = (float)i;
            out[2 * NITEMS + 2 * item + 1] = (float)j;
        }
    }
    __syncthreads();

    // ------------- stage B: layer2 GEMM (K=64), 8m x 8i tiles --------------
    {
        const int tm = tid >> 4;             // 0..15
        const int ti = tid & 15;             // 0..15
        const int m0 = tm * 8;
        const int i0 = ti * 8;

        float acc[8][8];
#pragma unroll
        for (int mm = 0; mm < 8; ++mm) {
            const float b = b2[m0 + mm];
#pragma unroll
            for (int ii = 0; ii < 8; ++ii) acc[mm][ii] = b;
        }

#pragma unroll 4
        for (int k = 0; k < 64; ++k) {
            const float4 a0 = *reinterpret_cast<const float4*>(g_W2t + k * 128 + m0);
            const float4 a1 = *reinterpret_cast<const float4*>(g_W2t + k * 128 + m0 + 4);
            const float4 x0 = *reinterpret_cast<const float4*>(H1s + k * H1STR + i0);
            const float4 x1 = *reinterpret_cast<const float4*>(H1s + k * H1STR + i0 + 4);
            const float av[8] = {a0.x, a0.y, a0.z, a0.w, a1.x, a1.y, a1.z, a1.w};
            const float xv[8] = {x0.x, x0.y, x0.z, x0.w, x1.x, x1.y, x1.z, x1.w};
#pragma unroll
            for (int mm = 0; mm < 8; ++mm)
#pragma unroll
                for (int ii = 0; ii < 8; ++ii)
                    acc[mm][ii] = fmaf(av[mm], xv[ii], acc[mm][ii]);
        }

#pragma unroll
        for (int mm = 0; mm < 8; ++mm) {
            float* dst = H2s + (m0 + mm) * H2STR + i0;
            float4 s0, s1;
            s0.x = fmaxf(acc[mm][0], 0.f); s0.y = fmaxf(acc[mm][1], 0.f);
            s0.z = fmaxf(acc[mm][2], 0.f); s0.w = fmaxf(acc[mm][3], 0.f);
            s1.x = fmaxf(acc[mm][4], 0.f); s1.y = fmaxf(acc[mm][5], 0.f);
            s1.z = fmaxf(acc[mm][6], 0.f); s1.w = fmaxf(acc[mm][7], 0.f);
            *reinterpret_cast<float4*>(dst)     = s0;
            *reinterpret_cast<float4*>(dst + 4) = s1;
        }
    }
    __syncthreads();

    // --------- stage C: layer3 GEMM (K=128), 4o x 8i tiles + layer4 --------
    {
        const int to = tid >> 4;             // 0..15 -> o group (4 each)
        const int ti = tid & 15;             // 0..15
        const int o0 = to * 4;
        const int i0 = ti * 8;

        float acc[4][8];
#pragma unroll
        for (int mm = 0; mm < 4; ++mm) {
            const float b = b3[o0 + mm];
#pragma unroll
            for (int ii = 0; ii < 8; ++ii) acc[mm][ii] = b;
        }

#pragma unroll 4
        for (int k = 0; k < 128; ++k) {
            const float4 a0 = *reinterpret_cast<const float4*>(g_W3t + k * 64 + o0);
            const float4 x0 = *reinterpret_cast<const float4*>(H2s + k * H2STR + i0);
            const float4 x1 = *reinterpret_cast<const float4*>(H2s + k * H2STR + i0 + 4);
            const float av[4] = {a0.x, a0.y, a0.z, a0.w};
            const float xv[8] = {x0.x, x0.y, x0.z, x0.w, x1.x, x1.y, x1.z, x1.w};
#pragma unroll
            for (int mm = 0; mm < 4; ++mm)
#pragma unroll
                for (int ii = 0; ii < 8; ++ii)
                    acc[mm][ii] = fmaf(av[mm], xv[ii], acc[mm][ii]);
        }

        // partial layer4 dot over this thread's 4 o's
        float w4v[4];
#pragma unroll
        for (int mm = 0; mm < 4; ++mm) w4v[mm] = W4[o0 + mm];

        __syncthreads();   // H2s still needed above; H1s (red) now reusable
#pragma unroll
        for (int ii = 0; ii < 8; ++ii) {
            float p = 0.f;
#pragma unroll
            for (int mm = 0; mm < 4; ++mm)
                p = fmaf(w4v[mm], fmaxf(acc[mm][ii], 0.f), p);
            red[to * H1STR + i0 + ii] = p;
        }
    }
    __syncthreads();

    // final: one thread per item sums 16 partials
    if (tid < TILE_I) {
        const int item = blockIdx.x * TILE_I + tid;
        float s = red[tid];
#pragma unroll
        for (int g = 1; g < 16; ++g) s += red[g * H1STR + tid];
        out[item] = (s + b4[0]) * masks[tid];
    }
}

extern "C" void kernel_launch(void* const* d_in, const int* in_sizes, int n_in,
                              void* d_out, int out_size) {
    const float* x  = (const float*)d_in[0];
    const float* r  = (const float*)d_in[1];
    const float* W1 = (const float*)d_in[2];
    const float* b1 = (const float*)d_in[3];
    const float* W2 = (const float*)d_in[4];
    const float* b2 = (const float*)d_in[5];
    const float* W3 = (const float*)d_in[6];
    const float* b3 = (const float*)d_in[7];
    const float* W4 = (const float*)d_in[8];
    const float* b4 = (const float*)d_in[9];
    float* out = (float*)d_out;

    cudaFuncSetAttribute(fused_mlp_kernel,
                         cudaFuncAttributeMaxDynamicSharedMemorySize, SMEM_BYTES);

    topk_kernel<<<NAG, T1>>>(x);
    transpose_kernel<<<1, 256>>>(W2, W3);
    fused_mlp_kernel<<<NITEMS / TILE_I, 256, SMEM_BYTES>>>(
        x, r, W1, b1, b2, b3, W4, b4, out);
}

// round 4
// speedup vs baseline: 2.2086x; 2.2086x over previous
#include <cuda_runtime.h>
#include <cstdint>

#define NAG   4096
#define TOPK  12
#define NSEL  13                 // extract 13, fix up ordering with real sqrt
#define NITEMS (NAG * TOPK)      // 49152
#define T1    256                // threads, topk kernel
#define EPT   16                 // elements per thread = 4096/256
#define LSTR  13                 // per-thread list stride in smem (13 entries)

// fused MLP tiling
#define TILE_I 64                // items per block
#define HSTR   68                // padded row stride (floats)
#define SMEM_FLOATS ((64 + 128) * HSTR)
#define SMEM_BYTES  (SMEM_FLOATS * 4)   // 52,224 B dynamic

__device__ int   g_topk_idx[NITEMS];
__device__ float g_W2t[64 * 128];        // [k][m]
__device__ float g_W3t[128 * 64];        // [k][o]

// ---------------------------------------------------------------------------
// Kernel 1: per-row top-12.
// Keys are (s_bits << 32) | j where s = (x0^2+1e-6)+(x1^2+1e-6) -- NO sqrt in
// the hot path. sqrt_rn is monotone, so (s,j) ordering differs from the
// reference (sqrt(s),j) ordering only when two s values round to the same
// sqrt; we extract the top-13 by (s,j), then re-sort those 13 by
// (sqrt_bits,j) and keep 12 -- exact reference semantics.
// Merge: proven round-1 structure (smem heads, block argmin) -- registers are
// never dynamically indexed.
// ---------------------------------------------------------------------------
__global__ void __launch_bounds__(T1) topk_kernel(const float* __restrict__ x) {
    const int i   = blockIdx.x;
    const int tid = threadIdx.x;
    const float* row = x + (size_t)i * (NAG * 4);

    unsigned long long keys[EPT];
#pragma unroll
    for (int t = 0; t < EPT; ++t) {
        const int j = tid + t * T1;
        const float2 v = *reinterpret_cast<const float2*>(row + (size_t)j * 4);
        const float s = __fadd_rn(__fadd_rn(__fmul_rn(v.x, v.x), 1e-6f),
                                  __fadd_rn(__fmul_rn(v.y, v.y), 1e-6f));
        keys[t] = ((unsigned long long)__float_as_uint(s) << 32) | (unsigned)j;
    }

    // fully-unrolled bitonic sort of 16 keys, ascending, static indices only
#pragma unroll
    for (int kk = 2; kk <= EPT; kk <<= 1) {
#pragma unroll
        for (int jj = kk >> 1; jj > 0; jj >>= 1) {
#pragma unroll
            for (int ii = 0; ii < EPT; ++ii) {
                const int ll = ii ^ jj;
                if (ll > ii) {
                    const bool up = ((ii & kk) == 0);
                    const unsigned long long a = keys[ii];
                    const unsigned long long b = keys[ll];
                    const bool sw = up ? (a > b) : (a < b);
                    if (sw) { keys[ii] = b; keys[ll] = a; }
                }
            }
        }
    }

    __shared__ unsigned long long skeys[T1 * LSTR];
#pragma unroll
    for (int t = 0; t < NSEL; ++t) skeys[tid * LSTR + t] = keys[t];

    __shared__ unsigned long long swarp[T1 / 32];
    __shared__ unsigned long long sbcast;
    __shared__ unsigned long long top13[NSEL];
    __syncthreads();

    // block merge: 13 passes of block-wide argmin over per-thread heads
    int head = 0;
#pragma unroll 1
    for (int pass = 0; pass < NSEL; ++pass) {
        const unsigned long long mykey =
            (head < NSEL) ? skeys[tid * LSTR + head] : 0xFFFFFFFFFFFFFFFFULL;
        unsigned long long v = mykey;
#pragma unroll
        for (int off = 16; off > 0; off >>= 1) {
            const unsigned long long o = __shfl_down_sync(0xffffffffu, v, off);
            v = (o < v) ? o : v;
        }
        if ((tid & 31) == 0) swarp[tid >> 5] = v;
        __syncthreads();
        if (tid == 0) {
            unsigned long long m = swarp[0];
#pragma unroll
            for (int w = 1; w < T1 / 32; ++w) m = (swarp[w] < m) ? swarp[w] : m;
            sbcast = m;
            top13[pass] = m;
        }
        __syncthreads();
        if (mykey == sbcast) head++;   // keys unique (low bits j) -> one thread
    }

    // fixup: re-key the 13 by (sqrt_bits, j), insertion sort, keep first 12
    if (tid == 0) {
        unsigned long long fk[NSEL];
#pragma unroll
        for (int t = 0; t < NSEL; ++t) {
            const unsigned long long k = top13[t];
            const float s = __uint_as_float((unsigned)(k >> 32));
            const float dn = __fsqrt_rn(s);
            fk[t] = ((unsigned long long)__float_as_uint(dn) << 32)
                  | (k & 0xFFFFFFFFULL);
        }
#pragma unroll
        for (int a = 1; a < NSEL; ++a) {
            const unsigned long long key = fk[a];
            int b = a - 1;
#pragma unroll
            for (int q = 0; q < NSEL - 1; ++q) {   // bounded shift loop
                if (b >= 0 && fk[b] > key) { fk[b + 1] = fk[b]; b--; }
            }
            fk[b + 1] = key;
        }
#pragma unroll
        for (int t = 0; t < TOPK; ++t)
            g_topk_idx[i * TOPK + t] = (int)(unsigned)(fk[t] & 0xFFFFFFFFULL);
    }
}

// ---------------------------------------------------------------------------
// Kernel T: transpose W2 [128m][64k] -> W2t [64k][128m],
//           W3 [64o][128m] -> W3t [128m][64o]
// ---------------------------------------------------------------------------
__global__ void __launch_bounds__(256) transpose_kernel(
    const float* __restrict__ W2, const float* __restrict__ W3)
{
    const int tid = threadIdx.x;
    for (int s = tid; s < 128 * 64; s += 256) {
        const int m = s >> 6, k = s & 63;
        g_W2t[k * 128 + m] = W2[s];
    }
    for (int s = tid; s < 64 * 128; s += 256) {
        const int o = s >> 7, m = s & 127;
        g_W3t[m * 64 + o] = W3[s];
    }
}

// ---------------------------------------------------------------------------
// Fused MLP kernel: per block = 64 items.
//   stage A: features + layer1 -> H1s (smem)
//   stage B: layer2 GEMM (K=64), 4m x 8i thread tiles -> H2s (smem)
//   stage C: layer3 GEMM (K=128), 4o x 4i tiles + fused layer4 reduction.
// Dynamic smem 52 KB -> 3 blocks/SM (24 warps).
// ---------------------------------------------------------------------------
__global__ void __launch_bounds__(256, 3) fused_mlp_kernel(
    const float* __restrict__ x,  const float* __restrict__ rp,
    const float* __restrict__ W1, const float* __restrict__ b1,
    const float* __restrict__ b2, const float* __restrict__ b3,
    const float* __restrict__ W4, const float* __restrict__ b4,
    float* __restrict__ out)
{
    extern __shared__ float smem[];
    float* H1s = smem;                   // [64][HSTR]
    float* H2s = smem + 64 * HSTR;       // [128][HSTR]
    float* red = smem;                   // reuse H1s area after stage B

    __shared__ float W1s[64 * 6];
    __shared__ float b1s[64];
    __shared__ float masks[TILE_I];

    const int tid = threadIdx.x;
    for (int s = tid; s < 384; s += 256) W1s[s] = W1[s];
    if (tid < 64) b1s[tid] = b1[tid];
    __syncthreads();

    // ---------------- stage A: features + layer1 (6 -> 64) ----------------
    {
        const int iloc = tid & 63;
        const int q    = tid >> 6;           // 4 threads per item
        const int item = blockIdx.x * TILE_I + iloc;
        const int i = item / TOPK;
        const int j = g_topk_idx[item];

        const float4 v = *reinterpret_cast<const float4*>(
            x + ((size_t)i * NAG + (size_t)j) * 4);
        const float s2 = __fadd_rn(__fadd_rn(__fmul_rn(v.x, v.x), 1e-4f),
                                   __fadd_rn(__fmul_rn(v.y, v.y), 1e-4f));
        const float dn = __fsqrt_rn(s2);
        const float r  = rp[0];
        const float mk = (dn <= 1.0f) ? 1.0f : 0.0f;
        const float f0 = v.x, f1 = v.y, f2 = v.z, f3 = v.w;
        const float f4 = (i == j) ? 1.0f : 0.0f;
        const float f5 = dn - r;

        const int o0 = q * 16;
#pragma unroll
        for (int oo = 0; oo < 16; ++oo) {
            const int o = o0 + oo;
            const float* wp = W1s + o * 6;
            float a = b1s[o];
            a = fmaf(wp[0], f0, a); a = fmaf(wp[1], f1, a); a = fmaf(wp[2], f2, a);
            a = fmaf(wp[3], f3, a); a = fmaf(wp[4], f4, a); a = fmaf(wp[5], f5, a);
            H1s[o * HSTR + iloc] = fmaxf(a, 0.0f);
        }

        if (q == 0) {
            masks[iloc] = mk;
            out[NITEMS + item] = mk;
            out[2 * NITEMS + 2 * item + 0] = (float)i;
            out[2 * NITEMS + 2 * item + 1] = (float)j;
        }
    }
    __syncthreads();

    // ------------- stage B: layer2 GEMM (K=64), 4m x 8i tiles --------------
    {
        const int tm = tid >> 3;             // 0..31
        const int ti = tid & 7;              // 0..7
        const int m0 = tm * 4;
        const int i0 = ti * 8;

        float acc[4][8];
#pragma unroll
        for (int mm = 0; mm < 4; ++mm) {
            const float b = b2[m0 + mm];
#pragma unroll
            for (int ii = 0; ii < 8; ++ii) acc[mm][ii] = b;
        }

#pragma unroll 4
        for (int k = 0; k < 64; ++k) {
            const float4 a0 = *reinterpret_cast<const float4*>(g_W2t + k * 128 + m0);
            const float4 x0 = *reinterpret_cast<const float4*>(H1s + k * HSTR + i0);
            const float4 x1 = *reinterpret_cast<const float4*>(H1s + k * HSTR + i0 + 4);
            const float av[4] = {a0.x, a0.y, a0.z, a0.w};
            const float xv[8] = {x0.x, x0.y, x0.z, x0.w, x1.x, x1.y, x1.z, x1.w};
#pragma unroll
            for (int mm = 0; mm < 4; ++mm)
#pragma unroll
                for (int ii = 0; ii < 8; ++ii)
                    acc[mm][ii] = fmaf(av[mm], xv[ii], acc[mm][ii]);
        }

#pragma unroll
        for (int mm = 0; mm < 4; ++mm) {
            float* dst = H2s + (m0 + mm) * HSTR + i0;
            float4 s0, s1;
            s0.x = fmaxf(acc[mm][0], 0.f); s0.y = fmaxf(acc[mm][1], 0.f);
            s0.z = fmaxf(acc[mm][2], 0.f); s0.w = fmaxf(acc[mm][3], 0.f);
            s1.x = fmaxf(acc[mm][4], 0.f); s1.y = fmaxf(acc[mm][5], 0.f);
            s1.z = fmaxf(acc[mm][6], 0.f); s1.w = fmaxf(acc[mm][7], 0.f);
            *reinterpret_cast<float4*>(dst)     = s0;
            *reinterpret_cast<float4*>(dst + 4) = s1;
        }
    }
    __syncthreads();

    // ------- stage C: layer3 GEMM (K=128), 4o x 4i tiles + layer4 ----------
    {
        const int to = tid >> 4;             // 0..15
        const int ti = tid & 15;             // 0..15
        const int o0 = to * 4;
        const int i0 = ti * 4;

        float acc[4][4];
#pragma unroll
        for (int mm = 0; mm < 4; ++mm) {
            const float b = b3[o0 + mm];
#pragma unroll
            for (int ii = 0; ii < 4; ++ii) acc[mm][ii] = b;
        }

#pragma unroll 4
        for (int k = 0; k < 128; ++k) {
            const float4 a0 = *reinterpret_cast<const float4*>(g_W3t + k * 64 + o0);
            const float4 x0 = *reinterpret_cast<const float4*>(H2s + k * HSTR + i0);
            const float av[4] = {a0.x, a0.y, a0.z, a0.w};
            const float xv[4] = {x0.x, x0.y, x0.z, x0.w};
#pragma unroll
            for (int mm = 0; mm < 4; ++mm)
#pragma unroll
                for (int ii = 0; ii < 4; ++ii)
                    acc[mm][ii] = fmaf(av[mm], xv[ii], acc[mm][ii]);
        }

        // partial layer4 dot over this thread's 4 o's (into reused H1s area)
        float w4v[4];
#pragma unroll
        for (int mm = 0; mm < 4; ++mm) w4v[mm] = W4[o0 + mm];

#pragma unroll
        for (int ii = 0; ii < 4; ++ii) {
            float p = 0.f;
#pragma unroll
            for (int mm = 0; mm < 4; ++mm)
                p = fmaf(w4v[mm], fmaxf(acc[mm][ii], 0.f), p);
            red[to * HSTR + i0 + ii] = p;
        }
    }
    __syncthreads();

    // final: one thread per item sums 16 partials
    if (tid < TILE_I) {
        const int item = blockIdx.x * TILE_I + tid;
        float s = red[tid];
#pragma unroll
        for (int g = 1; g < 16; ++g) s += red[g * HSTR + tid];
        out[item] = (s + b4[0]) * masks[tid];
    }
}

extern "C" void kernel_launch(void* const* d_in, const int* in_sizes, int n_in,
                              void* d_out, int out_size) {
    const float* x  = (const float*)d_in[0];
    const float* r  = (const float*)d_in[1];
    const float* W1 = (const float*)d_in[2];
    const float* b1 = (const float*)d_in[3];
    const float* W2 = (const float*)d_in[4];
    const float* b2 = (const float*)d_in[5];
    const float* W3 = (const float*)d_in[6];
    const float* b3 = (const float*)d_in[7];
    const float* W4 = (const float*)d_in[8];
    const float* b4 = (const float*)d_in[9];
    float* out = (float*)d_out;

    cudaFuncSetAttribute(fused_mlp_kernel,
                         cudaFuncAttributeMaxDynamicSharedMemorySize, SMEM_BYTES);

    topk_kernel<<<NAG, T1>>>(x);
    transpose_kernel<<<1, 256>>>(W2, W3);
    fused_mlp_kernel<<<NITEMS / TILE_I, 256, SMEM_BYTES>>>(
        x, r, W1, b1, b2, b3, W4, b4, out);
}